// round 9
// baseline (speedup 1.0000x reference)
#include <cuda_runtime.h>
#include <cstdint>

typedef unsigned long long ull;

// ---------------- problem constants ----------------
#define T_STEPS 2048
#define BATCH   64
#define FEAT    13
#define HID     300
#define OUT_MAIN (BATCH*T_STEPS*FEAT)
#define OUT_EMB_OFF OUT_MAIN

// ---------------- encoder config ----------------
#define CLUSTER 8
#define NB      4               // batch per cluster
#define HC      38              // hidden units per CTA (8*38 = 304)
#define KSPLIT  8               // k-splits per unit (lanes in shfl group)
#define TENC    (HC*KSPLIT)     // 304 threads, single uniform role
#define KPS     20              // real k-pairs per split (40 floats, incl x-fold)
#define SLOTP   21              // padded pair stride per split (bank-conflict-free)
#define NPAIR   (KSPLIT*SLOTP)  // 168 pairs per (buf, batch)

__device__ float g_hlast[BATCH*HID];
__device__ float g_emb[BATCH*HID];

// ---------------- helpers ----------------
__device__ __forceinline__ float sig_f(float x) {
    return __fdividef(1.f, 1.f + __expf(-x));
}
__device__ __forceinline__ float tanh_f(float x) {
    return 1.f - __fdividef(2.f, __expf(2.f * x) + 1.f);
}
__device__ __forceinline__ unsigned smem_u32(const void* p) {
    unsigned a;
    asm("{ .reg .u64 t; cvta.to.shared.u64 t, %1; cvt.u32.u64 %0, t; }"
        : "=r"(a) : "l"(p));
    return a;
}
__device__ __forceinline__ void cluster_sync_() {
    asm volatile("barrier.cluster.arrive.aligned;" ::: "memory");
    asm volatile("barrier.cluster.wait.aligned;" ::: "memory");
}
__device__ __forceinline__ ull pk2(float lo, float hi) {
    ull r;
    asm("mov.b64 %0, {%1, %2};" : "=l"(r) : "f"(lo), "f"(hi));
    return r;
}
__device__ __forceinline__ void fma2(ull& d, ull a, ull b) {
    asm("fma.rn.f32x2 %0, %1, %2, %0;" : "+l"(d) : "l"(a), "l"(b));
}
__device__ __forceinline__ float upks(ull v) {
    float lo, hi;
    asm("mov.b64 {%0, %1}, %2;" : "=f"(lo), "=f"(hi) : "l"(v));
    return lo + hi;
}
__device__ __forceinline__ unsigned mapa_(unsigned a, int rank) {
    unsigned r;
    asm("mapa.shared::cluster.u32 %0, %1, %2;" : "=r"(r) : "r"(a), "r"(rank));
    return r;
}
__device__ __forceinline__ void mbar_init(unsigned a, unsigned cnt) {
    asm volatile("mbarrier.init.shared.b64 [%0], %1;" :: "r"(a), "r"(cnt) : "memory");
}
__device__ __forceinline__ void mbar_wait_cl(unsigned a, unsigned par) {
    unsigned done;
    asm volatile(
        "{\n\t.reg .pred p;\n\t"
        "mbarrier.try_wait.parity.acquire.cluster.shared::cta.b64 p, [%1], %2;\n\t"
        "selp.b32 %0, 1, 0, p;\n\t}"
        : "=r"(done) : "r"(a), "r"(par) : "memory");
    if (!done) {
        asm volatile(
            "{\n\t.reg .pred P1;\n"
            "WAIT_%=:\n\t"
            "mbarrier.try_wait.parity.acquire.cluster.shared::cta.b64 P1, [%0], %1, 0x989680;\n\t"
            "@P1 bra DONE_%=;\n\t"
            "bra WAIT_%=;\n"
            "DONE_%=:\n\t}"
            :: "r"(a), "r"(par) : "memory");
    }
}
__device__ __forceinline__ void mbar_arrive_remote(unsigned local_addr, int rank) {
    unsigned ra = mapa_(local_addr, rank);
    asm volatile("mbarrier.arrive.release.cluster.shared::cluster.b64 _, [%0];"
                 :: "r"(ra) : "memory");
}
__device__ __forceinline__ void st_remote_f32(unsigned raddr, float v) {
    asm volatile("st.shared::cluster.f32 [%0], %1;" :: "r"(raddr), "f"(v) : "memory");
}
__device__ __forceinline__ void fence_cluster_() {
    asm volatile("fence.acq_rel.cluster;" ::: "memory");
}

// padded float index inside a (buf,batch) chunk for logical k in [0,320)
__device__ __forceinline__ int padded_fidx(int k) {
    int q = k >> 1;             // pair index
    int s = q / KPS;            // split
    int off = q % KPS;
    return (s * SLOTP + off) * 2 + (k & 1);
}

// weight fetch with x-fold: k<300 -> Whh; 304<=k<317 && g<2 -> Wih; else 0
__device__ __forceinline__ float wfetch(const float* __restrict__ Wih,
                                        const float* __restrict__ Whh,
                                        int g, int u, int k) {
    if (k < HID) return Whh[(g * HID + u) * HID + k];
    if (k >= 304 && k < 304 + FEAT && g < 2) return Wih[(g * HID + u) * FEAT + (k - 304)];
    return 0.f;
}

// ======================================================================
// Encoder: fused GEMM+reduce+gate, zero intra-CTA handoffs.
// tid = unit*8 + ksplit. Each thread: 3 gate rows x its 40-k slice in
// registers; shfl.bfly allreduce over the 8 ksplit lanes; gate lanes
// (ks even) compute gates and push h via st.shared::cluster; one
// __syncthreads + 8 release-arrives ends the step.
// ======================================================================
__global__ void __launch_bounds__(TENC, 1) __cluster_dims__(CLUSTER, 1, 1)
enc_kernel(const float* __restrict__ x,
           const float* __restrict__ Wih,
           const float* __restrict__ Whh,
           const float* __restrict__ bih,
           const float* __restrict__ bhh)
{
    __shared__ __align__(16) float2 hbuf[2][NB][NPAIR];   // 10752 B
    __shared__ ull mbars[2];

    const int tid = threadIdx.x;
    unsigned rank;
    asm("mov.u32 %0, %%cluster_ctarank;" : "=r"(rank));
    const int bg = (blockIdx.x / CLUSTER) * NB;

    // ---- zero h buffers (both, all padded slots) ----
    {
        float* hf = (float*)hbuf;
        for (int i = tid; i < 2 * NB * NPAIR * 2; i += TENC) hf[i] = 0.f;
    }
    __syncthreads();
    // ---- prime x(0) into buffer 0 ----
    if (tid < NB * FEAT) {
        int b = tid / FEAT, f = tid % FEAT;
        ((float*)&hbuf[0][b][0])[padded_fidx(304 + f)] =
            x[((long)(bg + b) * T_STEPS) * FEAT + f];
    }

    const int u   = tid / KSPLIT;     // 0..37
    const int ks  = tid % KSPLIT;     // 0..7
    const int u_g = (int)rank * HC + u;
    const bool active = u_g < HID;

    // ---- weights into registers: 3 gates x 20 k-pairs ----
    ull w[3][KPS];
#pragma unroll
    for (int g = 0; g < 3; g++)
#pragma unroll
        for (int kp = 0; kp < KPS; kp++) {
            int k0 = ks * 40 + 2 * kp;
            float a = active ? wfetch(Wih, Whh, g, u_g, k0) : 0.f;
            float b = active ? wfetch(Wih, Whh, g, u_g, k0 + 1) : 0.f;
            w[g][kp] = pk2(a, b);
        }
    // n-gate input weights (for gate lanes)
    ull wihn[7];
#pragma unroll
    for (int fp = 0; fp < 7; fp++) {
        float a = active ? Wih[(2 * HID + u_g) * FEAT + 2 * fp] : 0.f;
        float b = (active && 2 * fp + 1 < FEAT) ? Wih[(2 * HID + u_g) * FEAT + 2 * fp + 1] : 0.f;
        wihn[fp] = pk2(a, b);
    }
    float brz0 = 0.f, brz1 = 0.f, bin_ = 0.f, bhn_ = 0.f;
    if (active) {
        brz0 = bih[u_g]           + bhh[u_g];
        brz1 = bih[HID + u_g]     + bhh[HID + u_g];
        bin_ = bih[2 * HID + u_g];
        bhn_ = bhh[2 * HID + u_g];
    }

    // gate-lane identity: ks even -> owns batch b = ks>>1
    const int gb = ks >> 1;
    const bool gate_ok = active && ((ks & 1) == 0);
    const int hfidx4 = padded_fidx(u_g < HID ? u_g : 0) * 4;
    float h_keep = 0.f;

    // remote bases
    const unsigned hbase = smem_u32(hbuf);
    const unsigned barb  = smem_u32(mbars);
    unsigned rbase[CLUSTER];
#pragma unroll
    for (int c = 0; c < CLUSTER; c++) rbase[c] = mapa_(hbase, c);

    if (tid == 0) {
        mbar_init(barb, CLUSTER);
        mbar_init(barb + 8, CLUSTER);
    }
    // shfl mask: warp 9 has only lanes 0..15
    const unsigned wmask = (tid < 288) ? 0xffffffffu : 0x0000ffffu;

    __syncthreads();
    cluster_sync_();

    int par[2] = {0, 0};

    for (int t = 0; t < T_STEPS; t++) {
        const int p = t & 1;

        if (t) {
            mbar_wait_cl(barb + (unsigned)p * 8u, (unsigned)par[p]);
            par[p] ^= 1;
        }

        // x prefetch for t+1 (LDG issued early, consumed after GEMM)
        float xval = 0.f;
        int xb = 0, xf = 0;
        if (tid < NB * FEAT && t + 1 < T_STEPS) {
            xb = tid / FEAT; xf = tid % FEAT;
            xval = __ldg(&x[((long)(bg + xb) * T_STEPS + t + 1) * FEAT + xf]);
        }

        // ---- fused GEMM: 3 gates x 4 batches over this lane's k slice ----
        ull acc[NB][3];
#pragma unroll
        for (int b = 0; b < NB; b++)
#pragma unroll
            for (int g = 0; g < 3; g++) acc[b][g] = 0ull;
        {
            const ull* hb = (const ull*)&hbuf[p][0][ks * SLOTP];
#pragma unroll
            for (int kp = 0; kp < KPS; kp++) {
                ull h0 = hb[kp];
                ull h1 = hb[kp + NPAIR];
                ull h2 = hb[kp + 2 * NPAIR];
                ull h3 = hb[kp + 3 * NPAIR];
                fma2(acc[0][0], w[0][kp], h0);
                fma2(acc[0][1], w[1][kp], h0);
                fma2(acc[0][2], w[2][kp], h0);
                fma2(acc[1][0], w[0][kp], h1);
                fma2(acc[1][1], w[1][kp], h1);
                fma2(acc[1][2], w[2][kp], h1);
                fma2(acc[2][0], w[0][kp], h2);
                fma2(acc[2][1], w[1][kp], h2);
                fma2(acc[2][2], w[2][kp], h2);
                fma2(acc[3][0], w[0][kp], h3);
                fma2(acc[3][1], w[1][kp], h3);
                fma2(acc[3][2], w[2][kp], h3);
            }
        }
        // ---- warp-local allreduce across the 8 ksplit lanes ----
        float s[NB][3];
#pragma unroll
        for (int b = 0; b < NB; b++)
#pragma unroll
            for (int g = 0; g < 3; g++) s[b][g] = upks(acc[b][g]);
#pragma unroll
        for (int d = 1; d < KSPLIT; d <<= 1)
#pragma unroll
            for (int b = 0; b < NB; b++)
#pragma unroll
                for (int g = 0; g < 3; g++)
                    s[b][g] += __shfl_xor_sync(wmask, s[b][g], d);

        // ---- gates + remote push (gate lanes only) ----
        if (gate_ok) {
            // n-gate input dot from staged x (padded slots 147..153)
            ull d2 = 0ull;
            const ull* xq = (const ull*)&hbuf[p][gb][7 * SLOTP + 12];
#pragma unroll
            for (int fp = 0; fp < 7; fp++) fma2(d2, wihn[fp], xq[fp]);
            const float i_n = upks(d2);

            const float r = sig_f(s[gb][0] + brz0);
            const float z = sig_f(s[gb][1] + brz1);
            const float n = tanh_f(i_n + bin_ + r * (s[gb][2] + bhn_));
            const float hn = (1.f - z) * n + z * h_keep;
            h_keep = hn;

            if (t + 1 < T_STEPS) {
                const unsigned off = (unsigned)(((p ^ 1) * NB + gb) * NPAIR * 8) + (unsigned)hfidx4;
#pragma unroll
                for (int c = 0; c < CLUSTER; c++)
                    st_remote_f32(rbase[c] + off, hn);
            }
        }
        // stage x(t+1) locally into buffer p^1
        if (tid < NB * FEAT && t + 1 < T_STEPS)
            ((float*)&hbuf[p ^ 1][xb][0])[padded_fidx(304 + xf)] = xval;

        __syncthreads();
        if (tid < CLUSTER && t + 1 < T_STEPS) {
            fence_cluster_();
            mbar_arrive_remote(barb + (unsigned)((p ^ 1)) * 8u, tid);
        }
    }

    if (gate_ok) g_hlast[(bg + gb) * HID + u_g] = h_keep;

    // no CTA may exit while siblings may still write its SMEM
    cluster_sync_();
}

// ======================================================================
// fc + relu
// ======================================================================
__global__ void __launch_bounds__(128) fc_kernel(
    const float* __restrict__ fcW, const float* __restrict__ fcb,
    float* __restrict__ dout, int write_emb)
{
    __shared__ float hs[HID];
    const int b = blockIdx.x;
    const int tid = threadIdx.x;
    for (int k = tid; k < HID; k += 128) hs[k] = g_hlast[b * HID + k];
    __syncthreads();
    for (int j = tid; j < HID; j += 128) {
        float a = fcb[j];
        const float* w = fcW + j * HID;
#pragma unroll 4
        for (int k = 0; k < HID; k++) a = fmaf(w[k], hs[k], a);
        a = fmaxf(a, 0.f);
        g_emb[b * HID + j] = a;
        if (write_emb) dout[OUT_EMB_OFF + b * HID + j] = a;
    }
}

// ======================================================================
// Decoder: one warp per batch element, h broadcast via shfl.
// ======================================================================
__global__ void __launch_bounds__(32) dec_kernel(
    const float* __restrict__ dWih, const float* __restrict__ dWhh,
    const float* __restrict__ dbih, const float* __restrict__ dbhh,
    float* __restrict__ out)
{
    const int b = blockIdx.x;
    const int lane = threadIdx.x;

    float wr[FEAT], wz[FEAT], wn[FEAT];
    float gr0 = 0.f, gz0 = 0.f, gn0 = 0.f, bhn = 0.f, h = 0.f;

    if (lane < FEAT) {
        gr0 = dbih[lane]            + dbhh[lane];
        gz0 = dbih[FEAT + lane]     + dbhh[FEAT + lane];
        gn0 = dbih[2 * FEAT + lane];
        bhn = dbhh[2 * FEAT + lane];
        const float* e  = g_emb + b * HID;
        const float* w0 = dWih + lane * HID;
        const float* w1 = dWih + (FEAT + lane) * HID;
        const float* w2 = dWih + (2 * FEAT + lane) * HID;
#pragma unroll 4
        for (int k = 0; k < HID; k++) {
            float ev = e[k];
            gr0 = fmaf(w0[k], ev, gr0);
            gz0 = fmaf(w1[k], ev, gz0);
            gn0 = fmaf(w2[k], ev, gn0);
        }
#pragma unroll
        for (int k = 0; k < FEAT; k++) {
            wr[k] = dWhh[lane * FEAT + k];
            wz[k] = dWhh[(FEAT + lane) * FEAT + k];
            wn[k] = dWhh[(2 * FEAT + lane) * FEAT + k];
        }
    }

    float* ob = out + (long)b * T_STEPS * FEAT;
    for (int t = 0; t < T_STEPS; t++) {
        float sr = 0.f, sz = 0.f, sn = 0.f;
#pragma unroll
        for (int k = 0; k < FEAT; k++) {
            float hk = __shfl_sync(0xffffffffu, h, k);
            sr = fmaf(wr[k], hk, sr);
            sz = fmaf(wz[k], hk, sz);
            sn = fmaf(wn[k], hk, sn);
        }
        if (lane < FEAT) {
            float r = sig_f(gr0 + sr);
            float z = sig_f(gz0 + sz);
            float n = tanh_f(gn0 + r * (sn + bhn));
            h = (1.f - z) * n + z * h;
            ob[t * FEAT + lane] = h;
        }
    }
}

// ======================================================================
// launch
// ======================================================================
extern "C" void kernel_launch(void* const* d_in, const int* in_sizes, int n_in,
                              void* d_out, int out_size)
{
    const float* x        = (const float*)d_in[0];
    const float* enc_Wih  = (const float*)d_in[1];
    const float* enc_Whh  = (const float*)d_in[2];
    const float* enc_bih  = (const float*)d_in[3];
    const float* enc_bhh  = (const float*)d_in[4];
    const float* fc_W     = (const float*)d_in[5];
    const float* fc_b     = (const float*)d_in[6];
    const float* dec_Wih  = (const float*)d_in[7];
    const float* dec_Whh  = (const float*)d_in[8];
    const float* dec_bih  = (const float*)d_in[9];
    const float* dec_bhh  = (const float*)d_in[10];
    float* out = (float*)d_out;

    const int write_emb = (out_size >= OUT_MAIN + BATCH * HID) ? 1 : 0;

    enc_kernel<<<(BATCH / NB) * CLUSTER, TENC>>>(
        x, enc_Wih, enc_Whh, enc_bih, enc_bhh);
    fc_kernel<<<BATCH, 128>>>(fc_W, fc_b, out, write_emb);
    dec_kernel<<<BATCH, 32>>>(dec_Wih, dec_Whh, dec_bih, dec_bhh, out);
}

// round 10
// speedup vs baseline: 1.9023x; 1.9023x over previous
#include <cuda_runtime.h>
#include <cstdint>

typedef unsigned long long ull;

// ---------------- problem constants ----------------
#define T_STEPS 2048
#define BATCH   64
#define FEAT    13
#define HID     300
#define OUT_MAIN (BATCH*T_STEPS*FEAT)
#define OUT_EMB_OFF OUT_MAIN

// ---------------- encoder config ----------------
#define CLUSTER 8
#define NGROUP  2
#define NBG     2               // batch per group
#define NB      (NGROUP*NBG)    // 4 per cluster
#define TENC    576             // 480 gemm + 96 gate
#define NGEMM   480
#define HC      38              // hidden units per CTA chunk
#define ROWP    40              // padded rows per gate
#define R3      120
#define KSPLIT  8
#define KSEG2   19              // k-pairs per split (38 floats)
#define RG      60
#define CHUNKB  (NBG*HC*4)      // 304 B per CTA per group per step
#define EXPB    (CLUSTER*CHUNKB) // 2432 B expected per group-step

#define BAR_PART_A 1
#define BAR_PART_B 2
#define BAR_GATES  3

__device__ float g_hlast[BATCH*HID];
__device__ float g_emb[BATCH*HID];

// ---------------- helpers ----------------
__device__ __forceinline__ float sig_f(float x) {
    return __fdividef(1.f, 1.f + __expf(-x));
}
__device__ __forceinline__ float tanh_f(float x) {
    return 1.f - __fdividef(2.f, __expf(2.f * x) + 1.f);
}
__device__ __forceinline__ unsigned smem_u32(const void* p) {
    unsigned a;
    asm("{ .reg .u64 t; cvta.to.shared.u64 t, %1; cvt.u32.u64 %0, t; }"
        : "=r"(a) : "l"(p));
    return a;
}
__device__ __forceinline__ void cluster_sync_() {
    asm volatile("barrier.cluster.arrive.aligned;" ::: "memory");
    asm volatile("barrier.cluster.wait.aligned;" ::: "memory");
}
__device__ __forceinline__ ull pk2(float lo, float hi) {
    ull r;
    asm("mov.b64 %0, {%1, %2};" : "=l"(r) : "f"(lo), "f"(hi));
    return r;
}
__device__ __forceinline__ void fma2(ull& d, ull a, ull b) {
    asm("fma.rn.f32x2 %0, %1, %2, %0;" : "+l"(d) : "l"(a), "l"(b));
}
__device__ __forceinline__ float upks(ull v) {
    float lo, hi;
    asm("mov.b64 {%0, %1}, %2;" : "=f"(lo), "=f"(hi) : "l"(v));
    return lo + hi;
}
__device__ __forceinline__ unsigned mapa_(unsigned a, int rank) {
    unsigned r;
    asm("mapa.shared::cluster.u32 %0, %1, %2;" : "=r"(r) : "r"(a), "r"(rank));
    return r;
}
__device__ __forceinline__ void mbar_init(unsigned a, unsigned cnt) {
    asm volatile("mbarrier.init.shared.b64 [%0], %1;" :: "r"(a), "r"(cnt) : "memory");
}
__device__ __forceinline__ void mbar_expect(unsigned a, unsigned bytes) {
    asm volatile("mbarrier.arrive.expect_tx.shared.b64 _, [%0], %1;"
                 :: "r"(a), "r"(bytes) : "memory");
}
__device__ __forceinline__ void mbar_wait(unsigned a, unsigned par) {
    unsigned done;
    asm volatile(
        "{\n\t.reg .pred p;\n\t"
        "mbarrier.try_wait.parity.acquire.cta.shared::cta.b64 p, [%1], %2;\n\t"
        "selp.b32 %0, 1, 0, p;\n\t}"
        : "=r"(done) : "r"(a), "r"(par) : "memory");
    if (!done) {
        asm volatile(
            "{\n\t.reg .pred P1;\n"
            "WAIT_%=:\n\t"
            "mbarrier.try_wait.parity.acquire.cta.shared::cta.b64 P1, [%0], %1, 0x989680;\n\t"
            "@P1 bra DONE_%=;\n\t"
            "bra WAIT_%=;\n"
            "DONE_%=:\n\t}"
            :: "r"(a), "r"(par) : "memory");
    }
}
__device__ __forceinline__ void bulk_copy_cluster(unsigned dst, unsigned src,
                                                  unsigned bytes, unsigned rbar) {
    asm volatile(
        "cp.async.bulk.shared::cluster.shared::cta.mbarrier::complete_tx::bytes "
        "[%0], [%1], %2, [%3];"
        :: "r"(dst), "r"(src), "r"(bytes), "r"(rbar) : "memory");
}
__device__ __forceinline__ void fence_async_() {
    asm volatile("fence.proxy.async.shared::cta;" ::: "memory");
}
__device__ __forceinline__ void bar_arrive(int id, int cnt) {
    asm volatile("bar.arrive %0, %1;" :: "r"(id), "r"(cnt) : "memory");
}
__device__ __forceinline__ void bar_sync(int id, int cnt) {
    asm volatile("bar.sync %0, %1;" :: "r"(id), "r"(cnt) : "memory");
}

// ======================================================================
// Encoder: two-group pipeline + TMA bulk publish (single tx per dest).
// hbuf[g][buf][rank][batch][38] — each CTA's per-group chunk is one
// contiguous 304B block; publish = 8 parallel 304B bulk copies.
// ======================================================================
__global__ void __launch_bounds__(TENC, 1) __cluster_dims__(CLUSTER, 1, 1)
enc_kernel(const float* __restrict__ x,
           const float* __restrict__ Wih,
           const float* __restrict__ Whh,
           const float* __restrict__ bih,
           const float* __restrict__ bhh)
{
    __shared__ __align__(16) float  hbuf[NGROUP][2][CLUSTER][NBG][HC]; // 9728 B
    __shared__ __align__(16) float2 part[NGROUP][2][NBG][KSPLIT][RG];  // 30720 B
    __shared__ __align__(16) float  xst[NGROUP][2][NBG][14];           // 896 B
    __shared__ ull mbars[NGROUP][2];

    const int tid = threadIdx.x;
    unsigned rank;
    asm("mov.u32 %0, %%cluster_ctarank;" : "=r"(rank));
    const int bg = (blockIdx.x / CLUSTER) * NB;

    // ---- zero buffers ----
    {
        float* hf = (float*)hbuf;
        for (int i = tid; i < NGROUP * 2 * CLUSTER * NBG * HC; i += TENC) hf[i] = 0.f;
        float* xf = (float*)xst;
        for (int i = tid; i < NGROUP * 2 * NBG * 14; i += TENC) xf[i] = 0.f;
    }
    // prime x(0)
    if (tid < NGROUP * NBG * FEAT) {
        int g = tid / (NBG * FEAT), r = tid % (NBG * FEAT);
        int b = r / FEAT, f = r % FEAT;
        xst[g][0][b][f] = x[((long)(bg + g * NBG + b) * T_STEPS) * FEAT + f];
    }

    const unsigned barb  = smem_u32(&mbars[0][0]);
    const unsigned hbase = smem_u32(hbuf);
    if (tid == 0) {
#pragma unroll
        for (int i = 0; i < 4; i++) {
            mbar_init(barb + i * 8u, 1);
            mbar_expect(barb + i * 8u, EXPB);
        }
    }
    __syncthreads();

    if (tid < NGEMM) {
        // =================== GEMM role ===================
        const int ks = tid / RG;
        const int rg = tid % RG;
        const int row0 = rg * 2;
        ull w0[KSEG2], w1[KSEG2];
        {
            int ga = row0 / ROWP, ia = row0 % ROWP, ua = (int)rank * HC + ia;
            bool oka = (ia < HC) && (ua < HID);
            int gb2 = (row0 + 1) / ROWP, ib = (row0 + 1) % ROWP, ub = (int)rank * HC + ib;
            bool okb = (ib < HC) && (ub < HID);
#pragma unroll
            for (int kp = 0; kp < KSEG2; kp++) {
                int k0 = ks * HC + 2 * kp, k1 = k0 + 1;
                float a0 = (oka && k0 < HID) ? Whh[(ga * HID + ua) * HID + k0] : 0.f;
                float b0 = (oka && k1 < HID) ? Whh[(ga * HID + ua) * HID + k1] : 0.f;
                float a1 = (okb && k0 < HID) ? Whh[(gb2 * HID + ub) * HID + k0] : 0.f;
                float b1 = (okb && k1 < HID) ? Whh[(gb2 * HID + ub) * HID + k1] : 0.f;
                w0[kp] = pk2(a0, b0);
                w1[kp] = pk2(a1, b1);
            }
        }
        __syncthreads();
        cluster_sync_();

        for (int t = 0; t < T_STEPS; t++) {
            const int p = t & 1;
#pragma unroll
            for (int g = 0; g < NGROUP; g++) {
                if (t) {
                    const unsigned bw = barb + (unsigned)(g * 2 + ((t - 1) & 1)) * 8u;
                    mbar_wait(bw, (unsigned)(((t - 1) >> 1) & 1));
                    if (tid == 0) mbar_expect(bw, EXPB);
                }
                // GEMM over buf p: h chunks are rank-major, k = ks*38 + j
                const ull* hp = (const ull*)&hbuf[g][p][ks][0][0];
                ull a00 = 0, a01 = 0, a10 = 0, a11 = 0;
#pragma unroll
                for (int kp = 0; kp < KSEG2; kp++) {
                    ull h0 = hp[kp];
                    ull h1 = hp[kp + KSEG2];
                    fma2(a00, w0[kp], h0); fma2(a01, w1[kp], h0);
                    fma2(a10, w0[kp], h1); fma2(a11, w1[kp], h1);
                }
                part[g][p][0][ks][rg] = make_float2(upks(a00), upks(a01));
                part[g][p][1][ks][rg] = make_float2(upks(a10), upks(a11));
                bar_arrive(g == 0 ? BAR_PART_A : BAR_PART_B, TENC);
            }
        }
    } else {
        // =================== gate role (96 threads) ===================
        const int gt = tid - NGEMM;
        const int gb2 = gt / HC;          // 0/1 within group
        const int gi_ = gt % HC;
        const int u_g = (int)rank * HC + gi_;
        const bool active = (gt < NBG * HC) && (u_g < HID);

        ull wihr[3][7];
        float brz0 = 0.f, brz1 = 0.f, bin_ = 0.f, bhn_ = 0.f;
        float h_keep[NGROUP] = {0.f, 0.f};
        if (active) {
#pragma unroll
            for (int g = 0; g < 3; g++)
#pragma unroll
                for (int fp = 0; fp < 7; fp++) {
                    float a = Wih[(g * HID + u_g) * FEAT + 2 * fp];
                    float b = (2 * fp + 1 < FEAT) ? Wih[(g * HID + u_g) * FEAT + 2 * fp + 1] : 0.f;
                    wihr[g][fp] = pk2(a, b);
                }
            brz0 = bih[u_g]           + bhh[u_g];
            brz1 = bih[HID + u_g]     + bhh[HID + u_g];
            bin_ = bih[2 * HID + u_g];
            bhn_ = bhh[2 * HID + u_g];
        }
        __syncthreads();
        cluster_sync_();

        for (int t = 0; t < T_STEPS; t++) {
            const int p = t & 1;
            const int buf = p ^ 1;
#pragma unroll
            for (int g = 0; g < NGROUP; g++) {
                bar_sync(g == 0 ? BAR_PART_A : BAR_PART_B, TENC);

                // x prefetch for t+1 (this group's 2 batches)
                if (gt < NBG * FEAT && t + 1 < T_STEPS) {
                    int b = gt / FEAT, f = gt % FEAT;
                    xst[g][buf][b][f] =
                        __ldg(&x[((long)(bg + g * NBG + b) * T_STEPS + t + 1) * FEAT + f]);
                }

                if (active) {
                    const float* pf = (const float*)&part[g][p][gb2][0][0];
                    float s0 = 0.f, s1 = 0.f, s2 = 0.f;
#pragma unroll
                    for (int q = 0; q < KSPLIT; q++) {
                        const int base = q * R3;
                        s0 += pf[base + gi_];
                        s1 += pf[base + ROWP + gi_];
                        s2 += pf[base + 2 * ROWP + gi_];
                    }
                    ull d0 = 0, d1 = 0, d2 = 0;
                    const ull* xq = (const ull*)&xst[g][p][gb2][0];
#pragma unroll
                    for (int fp = 0; fp < 7; fp++) {
                        ull xv = xq[fp];
                        fma2(d0, wihr[0][fp], xv);
                        fma2(d1, wihr[1][fp], xv);
                        fma2(d2, wihr[2][fp], xv);
                    }
                    const float r = sig_f(upks(d0) + s0 + brz0);
                    const float z = sig_f(upks(d1) + s1 + brz1);
                    const float n = tanh_f(upks(d2) + bin_ + r * (s2 + bhn_));
                    const float hn = (1.f - z) * n + z * h_keep[g];
                    h_keep[g] = hn;
                    hbuf[g][buf][rank][gb2][gi_] = hn;   // local chunk write
                }
                bar_sync(BAR_GATES, TENC - NGEMM);
                if (t + 1 < T_STEPS && gt < CLUSTER) {
                    fence_async_();
                    const unsigned src = hbase
                        + (unsigned)((g * 2 + buf) * CLUSTER + (int)rank) * (unsigned)CHUNKB;
                    const unsigned rb = barb + (unsigned)(g * 2 + (t & 1)) * 8u;
                    bulk_copy_cluster(mapa_(src, gt), src, CHUNKB, mapa_(rb, gt));
                }
            }
        }

        if (active) {
#pragma unroll
            for (int g = 0; g < NGROUP; g++)
                g_hlast[(bg + g * NBG + gb2) * HID + u_g] = h_keep[g];
        }
    }

    // no CTA may exit while sibling TMA copies into it may be in flight
    cluster_sync_();
}

// ======================================================================
// fc + relu
// ======================================================================
__global__ void __launch_bounds__(128) fc_kernel(
    const float* __restrict__ fcW, const float* __restrict__ fcb,
    float* __restrict__ dout, int write_emb)
{
    __shared__ float hs[HID];
    const int b = blockIdx.x;
    const int tid = threadIdx.x;
    for (int k = tid; k < HID; k += 128) hs[k] = g_hlast[b * HID + k];
    __syncthreads();
    for (int j = tid; j < HID; j += 128) {
        float a = fcb[j];
        const float* w = fcW + j * HID;
#pragma unroll 4
        for (int k = 0; k < HID; k++) a = fmaf(w[k], hs[k], a);
        a = fmaxf(a, 0.f);
        g_emb[b * HID + j] = a;
        if (write_emb) dout[OUT_EMB_OFF + b * HID + j] = a;
    }
}

// ======================================================================
// Decoder: one warp per batch element, h broadcast via shfl.
// ======================================================================
__global__ void __launch_bounds__(32) dec_kernel(
    const float* __restrict__ dWih, const float* __restrict__ dWhh,
    const float* __restrict__ dbih, const float* __restrict__ dbhh,
    float* __restrict__ out)
{
    const int b = blockIdx.x;
    const int lane = threadIdx.x;

    float wr[FEAT], wz[FEAT], wn[FEAT];
    float gr0 = 0.f, gz0 = 0.f, gn0 = 0.f, bhn = 0.f, h = 0.f;

    if (lane < FEAT) {
        gr0 = dbih[lane]            + dbhh[lane];
        gz0 = dbih[FEAT + lane]     + dbhh[FEAT + lane];
        gn0 = dbih[2 * FEAT + lane];
        bhn = dbhh[2 * FEAT + lane];
        const float* e  = g_emb + b * HID;
        const float* w0 = dWih + lane * HID;
        const float* w1 = dWih + (FEAT + lane) * HID;
        const float* w2 = dWih + (2 * FEAT + lane) * HID;
#pragma unroll 4
        for (int k = 0; k < HID; k++) {
            float ev = e[k];
            gr0 = fmaf(w0[k], ev, gr0);
            gz0 = fmaf(w1[k], ev, gz0);
            gn0 = fmaf(w2[k], ev, gn0);
        }
#pragma unroll
        for (int k = 0; k < FEAT; k++) {
            wr[k] = dWhh[lane * FEAT + k];
            wz[k] = dWhh[(FEAT + lane) * FEAT + k];
            wn[k] = dWhh[(2 * FEAT + lane) * FEAT + k];
        }
    }

    float* ob = out + (long)b * T_STEPS * FEAT;
    for (int t = 0; t < T_STEPS; t++) {
        float sr = 0.f, sz = 0.f, sn = 0.f;
#pragma unroll
        for (int k = 0; k < FEAT; k++) {
            float hk = __shfl_sync(0xffffffffu, h, k);
            sr = fmaf(wr[k], hk, sr);
            sz = fmaf(wz[k], hk, sz);
            sn = fmaf(wn[k], hk, sn);
        }
        if (lane < FEAT) {
            float r = sig_f(gr0 + sr);
            float z = sig_f(gz0 + sz);
            float n = tanh_f(gn0 + r * (sn + bhn));
            h = (1.f - z) * n + z * h;
            ob[t * FEAT + lane] = h;
        }
    }
}

// ======================================================================
// launch
// ======================================================================
extern "C" void kernel_launch(void* const* d_in, const int* in_sizes, int n_in,
                              void* d_out, int out_size)
{
    const float* x        = (const float*)d_in[0];
    const float* enc_Wih  = (const float*)d_in[1];
    const float* enc_Whh  = (const float*)d_in[2];
    const float* enc_bih  = (const float*)d_in[3];
    const float* enc_bhh  = (const float*)d_in[4];
    const float* fc_W     = (const float*)d_in[5];
    const float* fc_b     = (const float*)d_in[6];
    const float* dec_Wih  = (const float*)d_in[7];
    const float* dec_Whh  = (const float*)d_in[8];
    const float* dec_bih  = (const float*)d_in[9];
    const float* dec_bhh  = (const float*)d_in[10];
    float* out = (float*)d_out;

    const int write_emb = (out_size >= OUT_MAIN + BATCH * HID) ? 1 : 0;

    enc_kernel<<<(BATCH / NB) * CLUSTER, TENC>>>(
        x, enc_Wih, enc_Whh, enc_bih, enc_bhh);
    fc_kernel<<<BATCH, 128>>>(fc_W, fc_b, out, write_emb);
    dec_kernel<<<BATCH, 32>>>(dec_Wih, dec_Whh, dec_bih, dec_bhh, out);
}